// round 4
// baseline (speedup 1.0000x reference)
#include <cuda_runtime.h>
#include <cstdint>
#include <cstddef>
#include <math.h>

// Problem constants (fixed by the reference: B=8, N=4096, NITER=4)
constexpr int B = 8;
constexpr int N = 4096;
constexpr int NITER = 4;
constexpr int BN = B * N;

constexpr int NCHUNK = 32;          // b-dimension split
constexpr int CB = N / NCHUNK;      // 128 rows of P per chunk
constexpr int TILE_A = 256;         // output columns per block
constexpr int BLOCK_A = 64;         // threads per block (4 cols each)
constexpr int NTILE = N / TILE_A;   // 16 a-tiles

// Static scratch (no allocations allowed)
__device__ float g_part[(size_t)NCHUNK * BN];   // 4 MB partial sums
__device__ float g_pred[BN];                    // current pred between iterations
__device__ unsigned int g_cnt[NTILE];           // arrival counters (zero-init; reset each iter)

using ull = unsigned long long;

__device__ __forceinline__ ull pk2(float x) {
    ull r; asm("mov.b64 %0, {%1, %1};" : "=l"(r) : "f"(x)); return r;
}
__device__ __forceinline__ ull fma2(ull a, ull b, ull c) {
    ull d; asm("fma.rn.f32x2 %0, %1, %2, %3;" : "=l"(d) : "l"(a), "l"(b), "l"(c)); return d;
}
__device__ __forceinline__ void upk2(ull v, float& lo, float& hi) {
    asm("mov.b64 {%0, %1}, %2;" : "=f"(lo), "=f"(hi) : "l"(v));
}

// One kernel per diffusion iteration.
// Grid (NTILE=16 a-tiles, NCHUNK=32 b-chunks) = 512 blocks x 64 threads.
// Phase 1: each block computes partial sums S_c[i,a] = sum_{b in chunk} pred[i,b]*P[b,a]
//          for its 256 a-columns (4 per thread, packed f32x2 over the 8 batches).
// Phase 2: the LAST block to arrive per a-tile combines the 32 planes (L2-hot),
//          applies v = 1 - exp(-S), seed-clamps, writes g_pred (+ d_out on last iter).
__global__ void __launch_bounds__(BLOCK_A) prop(
    const float* __restrict__ P, const float* __restrict__ pred0,
    const int2* __restrict__ seed, int nseeds,
    int use_ext, float* __restrict__ final_out)
{
    __shared__ ull s_p2[CB * 4];                  // pred chunk, batch-paired (4 KB)
    __shared__ int s_last;
    float* s_f = reinterpret_cast<float*>(s_p2);  // s_f[b*8 + i] = pred[i][b0+b]

    const int tid = threadIdx.x;
    const int c = blockIdx.y;
    const int b0 = c * CB;
    const float* __restrict__ pred = use_ext ? pred0 : g_pred;

#pragma unroll
    for (int j = 0; j < (CB * B) / BLOCK_A; j++) {   // 16 per thread
        int idx = j * BLOCK_A + tid;
        int i = idx >> 7;          // batch 0..7
        int b = idx & (CB - 1);    // local row 0..127
        s_f[b * 8 + i] = pred[i * N + b0 + b];
    }
    __syncthreads();

    const int a0 = blockIdx.x * TILE_A + tid * 4;
    const float4* __restrict__ p4 =
        reinterpret_cast<const float4*>(P + (size_t)b0 * N) + (a0 >> 2);

    ull acc[4][4];   // [a][batch-pair], f32x2
#pragma unroll
    for (int ai = 0; ai < 4; ai++)
#pragma unroll
        for (int p = 0; p < 4; p++) acc[ai][p] = 0ULL;   // (0.0f, 0.0f)

#pragma unroll 4
    for (int b = 0; b < CB; b++) {
        float4 pv = __ldg(&p4[(size_t)b * (N >> 2)]);
        ull P2[4] = { pk2(pv.x), pk2(pv.y), pk2(pv.z), pk2(pv.w) };
        ull np[4];
#pragma unroll
        for (int p = 0; p < 4; p++) np[p] = s_p2[b * 4 + p];
#pragma unroll
        for (int ai = 0; ai < 4; ai++)
#pragma unroll
            for (int p = 0; p < 4; p++)
                acc[ai][p] = fma2(P2[ai], np[p], acc[ai][p]);
    }

    // Store this chunk's partial-sum plane.
    float* outc = g_part + (size_t)c * BN;
#pragma unroll
    for (int p = 0; p < 4; p++) {
        float lo[4], hi[4];
#pragma unroll
        for (int ai = 0; ai < 4; ai++) upk2(acc[ai][p], lo[ai], hi[ai]);
        *reinterpret_cast<float4*>(outc + (size_t)(2 * p) * N + a0) =
            make_float4(lo[0], lo[1], lo[2], lo[3]);
        *reinterpret_cast<float4*>(outc + (size_t)(2 * p + 1) * N + a0) =
            make_float4(hi[0], hi[1], hi[2], hi[3]);
    }

    // Last-block-arrival detection (threadFenceReduction pattern).
    __syncthreads();
    if (tid == 0) {
        __threadfence();
        unsigned int old = atomicAdd(&g_cnt[blockIdx.x], 1u);
        s_last = (old == NCHUNK - 1) ? 1 : 0;
        if (s_last) __threadfence();   // acquire side
    }
    __syncthreads();
    if (!s_last) return;

    // ---- Combine phase (one block per a-tile) ----
    const int A0 = blockIdx.x * TILE_A;
    const float4* __restrict__ part4 = reinterpret_cast<const float4*>(g_part);
    float4* __restrict__ pred4 = reinterpret_cast<float4*>(g_pred);
    float4* __restrict__ out4 = reinterpret_cast<float4*>(final_out);

    // 512 output quads in this tile (64 aq x 8 i); 8 per thread.
    int addr[8];
    float4 acc4[8];
#pragma unroll
    for (int j = 0; j < 8; j++) {
        int q = tid + BLOCK_A * j;
        int i = q >> 6;
        int aq = q & 63;
        addr[j] = i * (N >> 2) + (A0 >> 2) + aq;
        acc4[j] = make_float4(0.f, 0.f, 0.f, 0.f);
    }
    // c-outer / j-inner: 8 independent load->add chains per c step (forced MLP=8).
    for (int cc = 0; cc < NCHUNK; cc++) {
#pragma unroll
        for (int j = 0; j < 8; j++) {
            float4 v = __ldg(&part4[(size_t)cc * (BN >> 2) + addr[j]]);
            acc4[j].x += v.x; acc4[j].y += v.y; acc4[j].z += v.z; acc4[j].w += v.w;
        }
    }
#pragma unroll
    for (int j = 0; j < 8; j++) {
        float4 s = acc4[j];
        float4 r;
        r.x = 1.0f - expf(-s.x);
        r.y = 1.0f - expf(-s.y);
        r.z = 1.0f - expf(-s.z);
        r.w = 1.0f - expf(-s.w);
        pred4[addr[j]] = r;
        if (final_out) out4[addr[j]] = r;
    }

    __syncthreads();   // order quad stores before seed overwrites
    for (int s = tid; s < nseeds; s += BLOCK_A) {
        int2 sd = seed[s];
        int n = sd.y;
        if (n >= A0 && n < A0 + TILE_A) {
            g_pred[sd.x * N + n] = 1.0f;
            if (final_out) final_out[sd.x * N + n] = 1.0f;
        }
    }
    if (tid == 0) g_cnt[blockIdx.x] = 0;   // reset for next iteration / next replay
}

extern "C" void kernel_launch(void* const* d_in, const int* in_sizes, int n_in,
                              void* d_out, int out_size) {
    const float* preds = (const float*)d_in[0];      // [B, N] fp32
    const float* P = (const float*)d_in[1];          // [N, N] fp32, P[b*N + a]
    const int2* seed = (const int2*)d_in[2];         // [NSEEDS, 2] int32 (b, n)
    int nseeds = in_sizes[2] / 2;
    float* out = (float*)d_out;

    dim3 grid(NTILE, NCHUNK);   // (16, 32) = 512 blocks

    for (int t = 0; t < NITER; t++) {
        prop<<<grid, BLOCK_A>>>(P, preds, seed, nseeds,
                                t == 0 ? 1 : 0,
                                (t == NITER - 1) ? out : nullptr);
    }
}

// round 5
// speedup vs baseline: 1.9956x; 1.9956x over previous
#include <cuda_runtime.h>
#include <cstdint>
#include <cstddef>
#include <math.h>

// Problem constants (fixed by the reference: B=8, N=4096, NITER=4)
constexpr int B = 8;
constexpr int N = 4096;
constexpr int NITER = 4;
constexpr int BN = B * N;

constexpr int NCHUNK = 32;          // b-dimension split
constexpr int CB = N / NCHUNK;      // 128 P-rows per chunk
constexpr int TILE_A = 128;         // output columns per block
constexpr int NTILE = N / TILE_A;   // 32 a-tiles
constexpr int BLOCK_A = 128;        // 32 col-quads x 4 batch-pairs

// Static scratch (no allocations allowed)
__device__ float g_part[(size_t)NCHUNK * BN];   // 4 MB partial sums
__device__ float g_pred[BN];                    // current pred between iterations

using ull = unsigned long long;

__device__ __forceinline__ ull pk2(float x) {
    ull r; asm("mov.b64 %0, {%1, %1};" : "=l"(r) : "f"(x)); return r;
}
__device__ __forceinline__ ull fma2(ull a, ull b, ull c) {
    ull d; asm("fma.rn.f32x2 %0, %1, %2, %3;" : "=l"(d) : "l"(a), "l"(b), "l"(c)); return d;
}
__device__ __forceinline__ void upk2(ull v, float& lo, float& hi) {
    asm("mov.b64 {%0, %1}, %2;" : "=f"(lo), "=f"(hi) : "l"(v));
}

// Kernel A: partial sums S_c[i,a] = sum_{b in chunk c} pred[i,b] * P[b,a].
// Grid (NTILE=32, NCHUNK=32) = 1024 blocks x 128 threads (28 warps/SM).
// Thread (q, p): column quad q (4 consecutive a), batch pair p (batches 2p, 2p+1).
// The 4 lanes of a quad load the SAME P float4 -> warp-level dedup (128B/warp).
__global__ void __launch_bounds__(BLOCK_A, 7) propA(
    const float* __restrict__ P, const float* __restrict__ pred0, int use_ext)
{
    __shared__ ull s_p2[CB * 4];                  // pred chunk, batch-paired (4 KB)
    float* s_f = reinterpret_cast<float*>(s_p2);  // s_f[b*8 + i] = pred[i][b0+b]

    const int tid = threadIdx.x;
    const int c = blockIdx.y;
    const int b0 = c * CB;
    const float* __restrict__ pred = use_ext ? pred0 : g_pred;

#pragma unroll
    for (int j = 0; j < (CB * B) / BLOCK_A; j++) {   // 8 per thread
        int idx = j * BLOCK_A + tid;
        int i = idx >> 7;          // batch 0..7
        int b = idx & (CB - 1);    // local row 0..127
        s_f[b * 8 + i] = pred[i * N + b0 + b];
    }
    __syncthreads();

    const int q = tid >> 2;        // col quad 0..31
    const int p = tid & 3;         // batch pair 0..3
    const int a0 = blockIdx.x * TILE_A + q * 4;
    const float4* __restrict__ p4 =
        reinterpret_cast<const float4*>(P + (size_t)b0 * N) + (a0 >> 2);

    ull acc0 = 0, acc1 = 0, acc2 = 0, acc3 = 0;   // f32x2 per column

#pragma unroll 4
    for (int b = 0; b < CB; b++) {
        float4 pv = __ldg(&p4[(size_t)b * (N >> 2)]);
        ull np = s_p2[b * 4 + p];
        acc0 = fma2(pk2(pv.x), np, acc0);
        acc1 = fma2(pk2(pv.y), np, acc1);
        acc2 = fma2(pk2(pv.z), np, acc2);
        acc3 = fma2(pk2(pv.w), np, acc3);
    }

    // Store: cols a0..a0+3 for batches 2p (lo) and 2p+1 (hi).
    float lo0, hi0, lo1, hi1, lo2, hi2, lo3, hi3;
    upk2(acc0, lo0, hi0); upk2(acc1, lo1, hi1);
    upk2(acc2, lo2, hi2); upk2(acc3, lo3, hi3);
    float* outc = g_part + (size_t)c * BN;
    *reinterpret_cast<float4*>(outc + (size_t)(2 * p) * N + a0) =
        make_float4(lo0, lo1, lo2, lo3);
    *reinterpret_cast<float4*>(outc + (size_t)(2 * p + 1) * N + a0) =
        make_float4(hi0, hi1, hi2, hi3);
}

// Kernel C: sum the 32 planes per output, v = 1 - exp(-S), seed clamp, write pred.
// One thread per output scalar; 32 stride-BN loads, fully coalesced, 8 indep chains.
__global__ void __launch_bounds__(256) propC(const int2* __restrict__ seed, int nseeds,
                                             float* __restrict__ final_out) {
    __shared__ int s_flat[128];
    const int tid = threadIdx.x;
    if (tid < nseeds) {
        int2 s = seed[tid];
        s_flat[tid] = s.x * N + s.y;
    }
    __syncthreads();

    const int g = blockIdx.x * 256 + tid;

    float a0 = 0.f, a1 = 0.f, a2 = 0.f, a3 = 0.f;
    float a4 = 0.f, a5 = 0.f, a6 = 0.f, a7 = 0.f;
#pragma unroll
    for (int c = 0; c < NCHUNK; c += 8) {
        a0 += __ldg(&g_part[(size_t)(c + 0) * BN + g]);
        a1 += __ldg(&g_part[(size_t)(c + 1) * BN + g]);
        a2 += __ldg(&g_part[(size_t)(c + 2) * BN + g]);
        a3 += __ldg(&g_part[(size_t)(c + 3) * BN + g]);
        a4 += __ldg(&g_part[(size_t)(c + 4) * BN + g]);
        a5 += __ldg(&g_part[(size_t)(c + 5) * BN + g]);
        a6 += __ldg(&g_part[(size_t)(c + 6) * BN + g]);
        a7 += __ldg(&g_part[(size_t)(c + 7) * BN + g]);
    }
    float s = ((a0 + a1) + (a2 + a3)) + ((a4 + a5) + (a6 + a7));
    float v = 1.0f - __expf(-s);
    for (int k = 0; k < nseeds; k++)
        if (s_flat[k] == g) v = 1.0f;
    g_pred[g] = v;
    if (final_out) final_out[g] = v;
}

extern "C" void kernel_launch(void* const* d_in, const int* in_sizes, int n_in,
                              void* d_out, int out_size) {
    const float* preds = (const float*)d_in[0];      // [B, N] fp32
    const float* P = (const float*)d_in[1];          // [N, N] fp32, P[b*N + a]
    const int2* seed = (const int2*)d_in[2];         // [NSEEDS, 2] int32 (b, n)
    int nseeds = in_sizes[2] / 2;
    if (nseeds > 128) nseeds = 128;
    float* out = (float*)d_out;

    dim3 gridA(NTILE, NCHUNK);   // (32, 32) = 1024 blocks
    dim3 gridC(BN / 256);        // 128 blocks

    for (int t = 0; t < NITER; t++) {
        propA<<<gridA, BLOCK_A>>>(P, preds, t == 0 ? 1 : 0);
        propC<<<gridC, 256>>>(seed, nseeds, (t == NITER - 1) ? out : nullptr);
    }
}